// round 14
// baseline (speedup 1.0000x reference)
#include <cuda_runtime.h>
#include <cuda_fp16.h>
#include <math.h>
#include <stdint.h>

// ---------------- problem constants ----------------
#define BATCH 2
#define SEQ   2048
#define DIM   1024
#define HEADS 16
#define DHEAD 64
#define FFI   4096
#define ROWS  (BATCH*SEQ)
#define CATW  5120               // 1024 attn + 4096 ff, combined row width

// ---------------- scratch ----------------
__device__ __half g_xn [(size_t)ROWS*DIM];
__device__ __half g_cn [(size_t)ROWS*DIM];
__device__ __half g_q  [(size_t)ROWS*DIM];
__device__ __half g_kv [(size_t)ROWS*2*DHEAD];
__device__ __half g_cat[(size_t)ROWS*CATW];      // [attn(1024) | ff(4096)] per row
__device__ __half g_w  [14811136];               // fp16 weights

#define WQFF_OFF  0                              // [9216][1024] (scaled Wq + interleaved Wff1)
#define WKV_OFF   9437184                        // [128][1024]
#define WFF2T_OFF 9568256                        // [1024][4096]
#define WOUTT_OFF 13762560                       // [1024][1024]

__device__ __forceinline__ unsigned smem_u32(const void* p) {
    unsigned sa;
    asm("{.reg .u64 t; cvta.to.shared.u64 t, %1; cvt.u32.u64 %0, t;}" : "=r"(sa) : "l"(p));
    return sa;
}
__device__ __forceinline__ void cp16(void* smem_ptr, const void* gptr) {
    asm volatile("cp.async.cg.shared.global [%0], [%1], 16;"
                 :: "r"(smem_u32(smem_ptr)), "l"(gptr));
}

#define MMA_F16(C0,C1,C2,C3,A0,A1,A2,A3,B0,B1) \
    asm volatile("mma.sync.aligned.m16n8k16.row.col.f32.f16.f16.f32 " \
        "{%0,%1,%2,%3},{%4,%5,%6,%7},{%8,%9},{%0,%1,%2,%3};" \
        : "+f"(C0), "+f"(C1), "+f"(C2), "+f"(C3) \
        : "r"(A0), "r"(A1), "r"(A2), "r"(A3), "r"(B0), "r"(B1))

#define LDSM_X4(R0,R1,R2,R3,ADDR) \
    asm volatile("ldmatrix.sync.aligned.m8n8.x4.shared.b16 {%0,%1,%2,%3}, [%4];" \
        : "=r"(R0), "=r"(R1), "=r"(R2), "=r"(R3) : "r"(ADDR))

// ---------------- preprocessing: transpose f32 -> half [N][K] -------------
__global__ void __launch_bounds__(256) transpose_half_kernel(const float* __restrict__ in,
                                                             __half* __restrict__ out,
                                                             int K, int N, int ostride,
                                                             float scale) {
    __shared__ float t[32][33];
    const int tx = threadIdx.x, ty = threadIdx.y;   // 32 x 8
    const int n0 = blockIdx.x * 32, k0 = blockIdx.y * 32;
#pragma unroll
    for (int i = 0; i < 32; i += 8)
        t[ty + i][tx] = in[(size_t)(k0 + ty + i) * N + n0 + tx];
    __syncthreads();
#pragma unroll
    for (int i = 0; i < 32; i += 8)
        out[(size_t)(n0 + ty + i) * ostride + k0 + tx] = __float2half(scale * t[tx][ty + i]);
}

// Wff1: transpose + interleave into rows 2j / 2j+1 (a / gate), K=1024
__global__ void __launch_bounds__(256) transpose_swiglu_kernel(const float* __restrict__ in,
                                                               __half* __restrict__ out) {
    __shared__ float ta[32][33], tg[32][33];
    const int tx = threadIdx.x, ty = threadIdx.y;
    const int j0 = blockIdx.x * 32, k0 = blockIdx.y * 32;
#pragma unroll
    for (int i = 0; i < 32; i += 8) {
        ta[ty + i][tx] = in[(size_t)(k0 + ty + i) * 8192 + j0 + tx];
        tg[ty + i][tx] = in[(size_t)(k0 + ty + i) * 8192 + 4096 + j0 + tx];
    }
    __syncthreads();
#pragma unroll
    for (int i = 0; i < 32; i += 8) {
        const int jj = j0 + ty + i;
        out[(size_t)(2 * jj)     * 1024 + k0 + tx] = __float2half(ta[tx][ty + i]);
        out[(size_t)(2 * jj + 1) * 1024 + k0 + tx] = __float2half(tg[tx][ty + i]);
    }
}

// ---------------- LayerNorm (f32 in -> half out) ----------------
__global__ void __launch_bounds__(256) ln_kernel(const float* __restrict__ in,
                                                 const float* __restrict__ g,
                                                 __half* __restrict__ out) {
    const int row = blockIdx.x;
    const int t = threadIdx.x;
    const float* p = in + (size_t)row * DIM;
    float4 v = *(const float4*)&p[t * 4];
    float s  = v.x + v.y + v.z + v.w;
    float sq = v.x*v.x + v.y*v.y + v.z*v.z + v.w*v.w;
#pragma unroll
    for (int off = 16; off; off >>= 1) {
        s  += __shfl_xor_sync(0xffffffffu, s,  off);
        sq += __shfl_xor_sync(0xffffffffu, sq, off);
    }
    __shared__ float rs[8], rq[8];
    if ((t & 31) == 0) { rs[t >> 5] = s; rq[t >> 5] = sq; }
    __syncthreads();
    float ts = 0.f, tq = 0.f;
#pragma unroll
    for (int i = 0; i < 8; i++) { ts += rs[i]; tq += rq[i]; }
    const float mu  = ts * (1.f / DIM);
    const float var = tq * (1.f / DIM) - mu * mu;
    const float rstd = rsqrtf(var + 1e-5f);
    float4 gv = *(const float4*)&g[t * 4];
    __half2* op = (__half2*)&out[(size_t)row * DIM + t * 4];
    op[0] = __floats2half2_rn((v.x - mu) * rstd * gv.x, (v.y - mu) * rstd * gv.y);
    op[1] = __floats2half2_rn((v.z - mu) * rstd * gv.z, (v.w - mu) * rstd * gv.w);
}

// ============ fp16 GEMM, 256x128 tiles, 512 threads (16 warps 4m x 4n) ====
// EPI 0: store f32; EPI 2: accumulate f32; EPI 5: QFF (q half / SwiGLU pairs)
#define H2S 72
#define H2_STG (256*H2S + 128*H2S)
#define HG2_SMEM_BYTES (2*H2_STG*2)

template<int EPI>
__global__ void __launch_bounds__(512) hgemm2_kernel(
        int M, int N, int K, int lda,
        const __half* __restrict__ A, const __half* __restrict__ Bt,
        void* __restrict__ Cv, __half* __restrict__ Cv2) {
    extern __shared__ __half smh[];
    const int tid = threadIdx.x, lane = tid & 31, wid = tid >> 5;
    const int wm = (wid >> 2) * 64, wn = (wid & 3) * 32;
    const int bm = blockIdx.y * 256, bn = blockIdx.x * 128;
    const int gr = lane >> 2, gq = lane & 3;

    float acc[4][4][4] = {};
    const int T = K / 64;

    auto issue = [&](int t) {
        const int s = t & 1;
        const int k0 = t * 64;
        __half* As = smh + s * H2_STG;
        __half* Bs = As + 256 * H2S;
#pragma unroll
        for (int p = 0; p < 4; p++) {
            const int lin = p * 512 + tid;
            const int row = lin >> 3, q8 = (lin & 7) * 8;
            cp16(&As[row * H2S + q8], &A[(size_t)(bm + row) * lda + k0 + q8]);
        }
#pragma unroll
        for (int p = 0; p < 2; p++) {
            const int lin = p * 512 + tid;
            const int row = lin >> 3, q8 = (lin & 7) * 8;
            cp16(&Bs[row * H2S + q8], &Bt[(size_t)(bn + row) * K + k0 + q8]);
        }
        asm volatile("cp.async.commit_group;");
    };

    issue(0);
    if (T > 1) issue(1);

    const int a_r = lane & 15, a_c = (lane >> 4) << 3;
    const int b_r = (lane & 7) + ((lane >> 4) & 1) * 8;
    const int b_c = ((lane >> 3) & 1) << 3;

    for (int t = 0; t < T; t++) {
        if (t + 1 < T) asm volatile("cp.async.wait_group 1;");
        else           asm volatile("cp.async.wait_group 0;");
        __syncthreads();

        const int s = t & 1;
        const __half* As = smh + s * H2_STG;
        const __half* Bs = As + 256 * H2S;
#pragma unroll
        for (int ks = 0; ks < 4; ks++) {
            const int k = ks * 16;
            unsigned a[4][4], b[4][2];
#pragma unroll
            for (int mi = 0; mi < 4; mi++) {
                const unsigned ad = smem_u32(&As[(wm + mi * 16 + a_r) * H2S + k + a_c]);
                LDSM_X4(a[mi][0], a[mi][1], a[mi][2], a[mi][3], ad);
            }
#pragma unroll
            for (int np = 0; np < 2; np++) {
                const unsigned ad = smem_u32(&Bs[(wn + np * 16 + b_r) * H2S + k + b_c]);
                LDSM_X4(b[2*np][0], b[2*np][1], b[2*np+1][0], b[2*np+1][1], ad);
            }
#pragma unroll
            for (int mi = 0; mi < 4; mi++)
#pragma unroll
                for (int ni = 0; ni < 4; ni++)
                    MMA_F16(acc[mi][ni][0], acc[mi][ni][1], acc[mi][ni][2], acc[mi][ni][3],
                            a[mi][0], a[mi][1], a[mi][2], a[mi][3], b[ni][0], b[ni][1]);
        }
        __syncthreads();
        if (t + 2 < T) issue(t + 2);
    }

#pragma unroll
    for (int mi = 0; mi < 4; mi++) {
#pragma unroll
        for (int ni = 0; ni < 4; ni++) {
            const int row0 = bm + wm + mi * 16 + gr;
            const int col  = bn + wn + ni * 8 + 2 * gq;
            if (EPI == 0 || EPI == 2) {
                float* C = (float*)Cv;
                float2* p0 = (float2*)&C[(size_t)row0 * N + col];
                float2* p1 = (float2*)&C[(size_t)(row0 + 8) * N + col];
                float2 v0 = make_float2(acc[mi][ni][0], acc[mi][ni][1]);
                float2 v1 = make_float2(acc[mi][ni][2], acc[mi][ni][3]);
                if (EPI == 2) {
                    float2 c0 = *p0, c1 = *p1;
                    v0.x += c0.x; v0.y += c0.y; v1.x += c1.x; v1.y += c1.y;
                }
                *p0 = v0; *p1 = v1;
            } else {  // EPI == 5 : QFF
                if (bn < 1024) {
                    __half* C = (__half*)Cv;
                    *(__half2*)&C[(size_t)row0 * 1024 + col] =
                        __floats2half2_rn(acc[mi][ni][0], acc[mi][ni][1]);
                    *(__half2*)&C[(size_t)(row0 + 8) * 1024 + col] =
                        __floats2half2_rn(acc[mi][ni][2], acc[mi][ni][3]);
                } else {
                    const int colh = (col - 1024) >> 1;
                    const float g0 = acc[mi][ni][1], g1 = acc[mi][ni][3];
                    Cv2[(size_t)row0 * CATW + colh] =
                        __float2half(acc[mi][ni][0] * (g0 / (1.f + __expf(-g0))));
                    Cv2[(size_t)(row0 + 8) * CATW + colh] =
                        __float2half(acc[mi][ni][2] * (g1 / (1.f + __expf(-g1))));
                }
            }
        }
    }
}

// ---------------- kv GEMM: 128x128 tiles (N=128 only) ----------------
#define HS 40
#define HSTAGE (128*HS*2)
#define HGEMM_SMEM_BYTES (3*HSTAGE*2)

__global__ void __launch_bounds__(256) kv_gemm_kernel(
        int M, int N, int K,
        const __half* __restrict__ A, const __half* __restrict__ Bt,
        __half* __restrict__ C) {
    extern __shared__ __half smh[];
    const int tid = threadIdx.x, lane = tid & 31, wid = tid >> 5;
    const int wm = (wid & 1) * 64, wn = (wid >> 1) * 32;
    const int bm = blockIdx.y * 128, bn = blockIdx.x * 128;
    const int gr = lane >> 2, gq = lane & 3;

    float acc[4][4][4] = {};
    const int T = K / 32;

    auto issue = [&](int t) {
        const int s = t % 3;
        const int k0 = t * 32;
        __half* As = smh + s * HSTAGE;
        __half* Bs = As + 128 * HS;
#pragma unroll
        for (int p = 0; p < 2; p++) {
            const int lin = p * 256 + tid;
            const int row = lin >> 2, q8 = (lin & 3) * 8;
            cp16(&As[row * HS + q8], &A [(size_t)(bm + row) * K + k0 + q8]);
            cp16(&Bs[row * HS + q8], &Bt[(size_t)(bn + row) * K + k0 + q8]);
        }
        asm volatile("cp.async.commit_group;");
    };

    issue(0);
    if (T > 1) issue(1);

    const int a_r = lane & 15, a_c = (lane >> 4) << 3;
    const int b_r = (lane & 7) + ((lane >> 4) & 1) * 8;
    const int b_c = ((lane >> 3) & 1) << 3;

    for (int t = 0; t < T; t++) {
        if (t + 1 < T) asm volatile("cp.async.wait_group 1;");
        else           asm volatile("cp.async.wait_group 0;");
        __syncthreads();
        if (t + 2 < T) issue(t + 2);

        const int s = t % 3;
        const __half* As = smh + s * HSTAGE;
        const __half* Bs = As + 128 * HS;
#pragma unroll
        for (int ks = 0; ks < 2; ks++) {
            const int k = ks * 16;
            unsigned a[4][4], b[4][2];
#pragma unroll
            for (int mi = 0; mi < 4; mi++) {
                const unsigned ad = smem_u32(&As[(wm + mi * 16 + a_r) * HS + k + a_c]);
                LDSM_X4(a[mi][0], a[mi][1], a[mi][2], a[mi][3], ad);
            }
#pragma unroll
            for (int np = 0; np < 2; np++) {
                const unsigned ad = smem_u32(&Bs[(wn + np * 16 + b_r) * HS + k + b_c]);
                LDSM_X4(b[2*np][0], b[2*np][1], b[2*np+1][0], b[2*np+1][1], ad);
            }
#pragma unroll
            for (int mi = 0; mi < 4; mi++)
#pragma unroll
                for (int ni = 0; ni < 4; ni++)
                    MMA_F16(acc[mi][ni][0], acc[mi][ni][1], acc[mi][ni][2], acc[mi][ni][3],
                            a[mi][0], a[mi][1], a[mi][2], a[mi][3], b[ni][0], b[ni][1]);
        }
        __syncthreads();
    }

#pragma unroll
    for (int mi = 0; mi < 4; mi++) {
#pragma unroll
        for (int ni = 0; ni < 4; ni++) {
            const int row0 = bm + wm + mi * 16 + gr;
            const int col  = bn + wn + ni * 8 + 2 * gq;
            *(__half2*)&C[(size_t)row0 * N + col] =
                __floats2half2_rn(acc[mi][ni][0], acc[mi][ni][1]);
            *(__half2*)&C[(size_t)(row0 + 8) * N + col] =
                __floats2half2_rn(acc[mi][ni][2], acc[mi][ni][3]);
        }
    }
}

// ---------------- flash attention, fp16 mma + ldmatrix --------------------
#define AQS 72
#define AOFF_P  4608
#define AOFF_ST 9216
#define ASTAGE  9216
#define AOFF_MK 27648
#define ATT_SMEM_BYTES (AOFF_MK*2 + 2*64*4)

__global__ void __launch_bounds__(128) attn_kernel(const __half* __restrict__ q,
                                                   const __half* __restrict__ kv,
                                                   const int* __restrict__ mask,
                                                   __half* __restrict__ out) {
    extern __shared__ __half smh[];
    __half* sQ = smh;
    __half* sP = smh + AOFF_P;

    const int tid = threadIdx.x, lane = tid & 31, wid = tid >> 5;
    const int gr = lane >> 2, gq = lane & 3;
    const int wm = wid * 16;
    const int qt = blockIdx.x, h = blockIdx.y, b = blockIdx.z;
    const size_t qbase = ((size_t)(b * SEQ + qt * 64)) * DIM + h * DHEAD;
    const size_t obase = ((size_t)(b * SEQ + qt * 64)) * CATW + h * DHEAD;

    const int a_r = lane & 15, a_c = (lane >> 4) << 3;
    const int b_r = (lane & 7) + ((lane >> 4) & 1) * 8;
    const int b_c = ((lane >> 3) & 1) << 3;

#pragma unroll
    for (int p = 0; p < 4; p++) {
        const int lin = p * 128 + tid;
        const int r = lin >> 3, c8 = (lin & 7) * 8;
        *(uint4*)&sQ[r * AQS + c8] = *(const uint4*)&q[qbase + (size_t)r * DIM + c8];
    }

    auto issue = [&](int jt, int s) {
        __half* sK = smh + AOFF_ST + s * ASTAGE;
        __half* sV = sK + 64 * AQS;
        int*   sMk = (int*)(smh + AOFF_MK) + s * 64;
        const size_t kbase = (size_t)(b * SEQ + jt * 64) * 128;
#pragma unroll
        for (int p = 0; p < 8; p++) {
            const int lin = p * 128 + tid;
            const int j = lin >> 4, c8 = (lin & 15) * 8;
            const __half* src = &kv[kbase + (size_t)j * 128 + c8];
            if (c8 < 64) cp16(&sK[j * AQS + c8], src);
            else         cp16(&sV[j * AQS + c8 - 64], src);
        }
        if (tid < 16) cp16(&sMk[tid * 4], &mask[b * SEQ + jt * 64 + tid * 4]);
        asm volatile("cp.async.commit_group;");
    };

    issue(0, 0);

    float m0 = -1e30f, m1 = -1e30f, l0 = 0.f, l1 = 0.f;
    float o[8][4];
#pragma unroll
    for (int d = 0; d < 8; d++)
#pragma unroll
        for (int j = 0; j < 4; j++) o[d][j] = 0.f;

    for (int jt = 0; jt < SEQ / 64; jt++) {
        if (jt + 1 < SEQ / 64) {
            issue(jt + 1, (jt + 1) & 1);
            asm volatile("cp.async.wait_group 1;");
        } else {
            asm volatile("cp.async.wait_group 0;");
        }
        __syncthreads();

        const int s = jt & 1;
        const __half* sK = smh + AOFF_ST + s * ASTAGE;
        const __half* sV = sK + 64 * AQS;
        const int*   sMk = (const int*)(smh + AOFF_MK) + s * 64;

        float sc[8][4];
#pragma unroll
        for (int n = 0; n < 8; n++)
#pragma unroll
            for (int j = 0; j < 4; j++) sc[n][j] = 0.f;

#pragma unroll
        for (int ks = 0; ks < 4; ks++) {
            const int k = ks * 16;
            unsigned a0, a1, a2, a3;
            LDSM_X4(a0, a1, a2, a3, smem_u32(&sQ[(wm + a_r) * AQS + k + a_c]));
#pragma unroll
            for (int np = 0; np < 4; np++) {
                unsigned b0, b1, b2, b3;
                LDSM_X4(b0, b1, b2, b3, smem_u32(&sK[(np * 16 + b_r) * AQS + k + b_c]));
                MMA_F16(sc[2*np][0], sc[2*np][1], sc[2*np][2], sc[2*np][3],
                        a0, a1, a2, a3, b0, b1);
                MMA_F16(sc[2*np+1][0], sc[2*np+1][1], sc[2*np+1][2], sc[2*np+1][3],
                        a0, a1, a2, a3, b2, b3);
            }
        }

#pragma unroll
        for (int n = 0; n < 8; n++) {
            const int c0 = n * 8 + 2 * gq;
            if (sMk[c0] == 0)     { sc[n][0] = -1e30f; sc[n][2] = -1e30f; }
            if (sMk[c0 + 1] == 0) { sc[n][1] = -1e30f; sc[n][3] = -1e30f; }
        }
        float mx0 = -1e30f, mx1 = -1e30f;
#pragma unroll
        for (int n = 0; n < 8; n++) {
            mx0 = fmaxf(mx0, fmaxf(sc[n][0], sc[n][1]));
            mx1 = fmaxf(mx1, fmaxf(sc[n][2], sc[n][3]));
        }
        mx0 = fmaxf(mx0, __shfl_xor_sync(0xffffffffu, mx0, 1));
        mx0 = fmaxf(mx0, __shfl_xor_sync(0xffffffffu, mx0, 2));
        mx1 = fmaxf(mx1, __shfl_xor_sync(0xffffffffu, mx1, 1));
        mx1 = fmaxf(mx1, __shfl_xor_sync(0xffffffffu, mx1, 2));
        const float mn0 = fmaxf(m0, mx0), mn1 = fmaxf(m1, mx1);
        const float corr0 = __expf(m0 - mn0), corr1 = __expf(m1 - mn1);
        float rs0 = 0.f, rs1 = 0.f;
#pragma unroll
        for (int n = 0; n < 8; n++) {
            float p0 = __expf(sc[n][0] - mn0);
            float p1 = __expf(sc[n][1] - mn0);
            float p2 = __expf(sc[n][2] - mn1);
            float p3 = __expf(sc[n][3] - mn1);
            rs0 += p0 + p1; rs1 += p2 + p3;
            *(__half2*)&sP[(wm + gr) * AQS + n * 8 + 2 * gq] = __floats2half2_rn(p0, p1);
            *(__half2*)&sP[(wm + gr + 8) * AQS + n * 8 + 2 * gq] = __floats2half2_rn(p2, p3);
        }
        rs0 += __shfl_xor_sync(0xffffffffu, rs0, 1);
        rs0 += __shfl_xor_sync(0xffffffffu, rs0, 2);
        rs1 += __shfl_xor_sync(0xffffffffu, rs1, 1);
        rs1 += __shfl_xor_sync(0xffffffffu, rs1, 2);
        l0 = l0 * corr0 + rs0; m0 = mn0;
        l1 = l1 * corr1 + rs1; m1 = mn1;
#pragma unroll
        for (int d = 0; d < 8; d++) {
            o[d][0] *= corr0; o[d][1] *= corr0;
            o[d][2] *= corr1; o[d][3] *= corr1;
        }
        __syncwarp();

#pragma unroll
        for (int ks = 0; ks < 4; ks++) {
            const int kc = ks * 16;
            unsigned a0, a1, a2, a3;
            LDSM_X4(a0, a1, a2, a3, smem_u32(&sP[(wm + a_r) * AQS + kc + a_c]));
            const int vrow = kc + (lane & 7) + ((lane >> 3) & 1) * 8;
            const int vcb  = ((lane >> 4) & 1) * 8;
#pragma unroll
            for (int dp = 0; dp < 4; dp++) {
                unsigned b0, b1, b2, b3;
                const unsigned addr = smem_u32(&sV[vrow * AQS + dp * 16 + vcb]);
                asm volatile(
                    "ldmatrix.sync.aligned.m8n8.x4.trans.shared.b16 {%0,%1,%2,%3}, [%4];"
                    : "=r"(b0), "=r"(b1), "=r"(b2), "=r"(b3) : "r"(addr));
                MMA_F16(o[dp*2][0], o[dp*2][1], o[dp*2][2], o[dp*2][3],
                        a0, a1, a2, a3, b0, b1);
                MMA_F16(o[dp*2+1][0], o[dp*2+1][1], o[dp*2+1][2], o[dp*2+1][3],
                        a0, a1, a2, a3, b2, b3);
            }
        }
        __syncthreads();
    }

    const float inv0 = 1.f / l0, inv1 = 1.f / l1;
#pragma unroll
    for (int dt = 0; dt < 8; dt++) {
        const int col = dt * 8 + 2 * gq;
        *(__half2*)&out[obase + (size_t)(wm + gr) * CATW + col] =
            __floats2half2_rn(o[dt][0] * inv0, o[dt][1] * inv0);
        *(__half2*)&out[obase + (size_t)(wm + gr + 8) * CATW + col] =
            __floats2half2_rn(o[dt][2] * inv1, o[dt][3] * inv1);
    }
}

// ---------------- launch --------------------------------------------------
extern "C" void kernel_launch(void* const* d_in, const int* in_sizes, int n_in,
                              void* d_out, int out_size) {
    (void)in_sizes; (void)n_in; (void)out_size;
    const float* x        = (const float*)d_in[0];
    const float* context  = (const float*)d_in[1];
    const int*   mask     = (const int*)  d_in[2];
    const float* gamma    = (const float*)d_in[3];
    const float* ctxgamma = (const float*)d_in[4];
    const float* Wq       = (const float*)d_in[5];
    const float* Wkv      = (const float*)d_in[6];
    const float* Wout     = (const float*)d_in[7];
    const float* Wff1     = (const float*)d_in[8];
    const float* Wff2     = (const float*)d_in[9];
    float* out = (float*)d_out;

    __half *xn, *cn, *qb, *kvb, *cat, *w;
    cudaGetSymbolAddress((void**)&xn,  g_xn);
    cudaGetSymbolAddress((void**)&cn,  g_cn);
    cudaGetSymbolAddress((void**)&qb,  g_q);
    cudaGetSymbolAddress((void**)&kvb, g_kv);
    cudaGetSymbolAddress((void**)&cat, g_cat);
    cudaGetSymbolAddress((void**)&w,   g_w);

    cudaFuncSetAttribute(attn_kernel, cudaFuncAttributeMaxDynamicSharedMemorySize, ATT_SMEM_BYTES);
    cudaFuncSetAttribute(kv_gemm_kernel, cudaFuncAttributeMaxDynamicSharedMemorySize, HGEMM_SMEM_BYTES);
    cudaFuncSetAttribute(hgemm2_kernel<0>, cudaFuncAttributeMaxDynamicSharedMemorySize, HG2_SMEM_BYTES);
    cudaFuncSetAttribute(hgemm2_kernel<2>, cudaFuncAttributeMaxDynamicSharedMemorySize, HG2_SMEM_BYTES);
    cudaFuncSetAttribute(hgemm2_kernel<5>, cudaFuncAttributeMaxDynamicSharedMemorySize, HG2_SMEM_BYTES);

    cudaStream_t s1;
    cudaStreamCreateWithFlags(&s1, cudaStreamNonBlocking);
    cudaEvent_t eFork, eKV, eQFF, eOF;
    cudaEventCreateWithFlags(&eFork, cudaEventDisableTiming);
    cudaEventCreateWithFlags(&eKV,   cudaEventDisableTiming);
    cudaEventCreateWithFlags(&eQFF,  cudaEventDisableTiming);
    cudaEventCreateWithFlags(&eOF,   cudaEventDisableTiming);

    dim3 tb(32, 8);

    cudaEventRecord(eFork, 0);
    cudaStreamWaitEvent(s1, eFork, 0);

    // ---- main stream: x chain -> QFF GEMM ----
    ln_kernel<<<ROWS, 256>>>(x, gamma, xn);
    transpose_half_kernel<<<dim3(1024/32, 1024/32), tb>>>(Wq, w + WQFF_OFF, 1024, 1024, 1024, 0.125f);
    transpose_swiglu_kernel<<<dim3(4096/32, 1024/32), tb>>>(Wff1, w + WQFF_OFF + 1024*1024);
    hgemm2_kernel<5><<<dim3(9216/128, ROWS/256), 512, HG2_SMEM_BYTES>>>(
        ROWS, 9216, DIM, DIM, xn, w + WQFF_OFF, qb, cat + 1024);
    cudaEventRecord(eQFF, 0);

    // ---- side stream: ctx chain, weight prep, then OUT_ff overlapping attention
    ln_kernel<<<ROWS, 256, 0, s1>>>(context, ctxgamma, cn);
    transpose_half_kernel<<<dim3(128/32, 1024/32), tb, 0, s1>>>(Wkv, w + WKV_OFF, 1024, 128, 1024, 1.f);
    kv_gemm_kernel<<<dim3(1, ROWS/128), 256, HGEMM_SMEM_BYTES, s1>>>(
        ROWS, 2*DHEAD, DIM, cn, w + WKV_OFF, kvb);
    cudaEventRecord(eKV, s1);
    transpose_half_kernel<<<dim3(1024/32, 4096/32), tb, 0, s1>>>(Wff2, w + WFF2T_OFF, 4096, 1024, 4096, 1.f);
    transpose_half_kernel<<<dim3(1024/32, 1024/32), tb, 0, s1>>>(Wout, w + WOUTT_OFF, 1024, 1024, 1024, 1.f);
    cudaStreamWaitEvent(s1, eQFF, 0);
    // OUT_ff: out = ff @ Wff2 (K=4096), runs concurrently with attention
    hgemm2_kernel<0><<<dim3(DIM/128, ROWS/256), 512, HG2_SMEM_BYTES, s1>>>(
        ROWS, DIM, FFI, CATW, cat + 1024, w + WFF2T_OFF, out, nullptr);
    cudaEventRecord(eOF, s1);

    // ---- main stream: attention (after QFF; needs kv) ----
    cudaStreamWaitEvent(0, eKV, 0);
    attn_kernel<<<dim3(SEQ/64, HEADS, BATCH), 128, ATT_SMEM_BYTES>>>(qb, kvb, mask, cat);

    // OUT_attn: out += attn @ Wout (K=1024, A strided by CATW in g_cat)
    cudaStreamWaitEvent(0, eOF, 0);
    hgemm2_kernel<2><<<dim3(DIM/128, ROWS/256), 512, HG2_SMEM_BYTES>>>(
        ROWS, DIM, DIM, CATW, cat, w + WOUTT_OFF, out, nullptr);

    cudaEventDestroy(eFork);
    cudaEventDestroy(eKV);
    cudaEventDestroy(eQFF);
    cudaEventDestroy(eOF);
    cudaStreamDestroy(s1);
}

// round 15
// speedup vs baseline: 1.0203x; 1.0203x over previous
#include <cuda_runtime.h>
#include <cuda_fp16.h>
#include <math.h>
#include <stdint.h>

// ---------------- problem constants ----------------
#define BATCH 2
#define SEQ   2048
#define DIM   1024
#define HEADS 16
#define DHEAD 64
#define FFI   4096
#define ROWS  (BATCH*SEQ)
#define CATW  5120               // 1024 attn + 4096 ff, combined row width

// ---------------- scratch ----------------
__device__ __half g_xn [(size_t)ROWS*DIM];
__device__ __half g_cn [(size_t)ROWS*DIM];
__device__ __half g_q  [(size_t)ROWS*DIM];
__device__ __half g_kv [(size_t)ROWS*2*DHEAD];
__device__ __half g_cat[(size_t)ROWS*CATW];      // [attn(1024) | ff(4096)] per row
__device__ __half g_w  [14811136];               // fp16 weights

#define WQFF_OFF  0                              // [9216][1024] (scaled Wq + interleaved Wff1)
#define WKV_OFF   9437184                        // [128][1024]
#define WOUT2_OFF 9568256                        // [1024][5120]  (WoutT | Wff2T)

__device__ __forceinline__ unsigned smem_u32(const void* p) {
    unsigned sa;
    asm("{.reg .u64 t; cvta.to.shared.u64 t, %1; cvt.u32.u64 %0, t;}" : "=r"(sa) : "l"(p));
    return sa;
}
__device__ __forceinline__ void cp16(void* smem_ptr, const void* gptr) {
    asm volatile("cp.async.cg.shared.global [%0], [%1], 16;"
                 :: "r"(smem_u32(smem_ptr)), "l"(gptr));
}

#define MMA_F16(C0,C1,C2,C3,A0,A1,A2,A3,B0,B1) \
    asm volatile("mma.sync.aligned.m16n8k16.row.col.f32.f16.f16.f32 " \
        "{%0,%1,%2,%3},{%4,%5,%6,%7},{%8,%9},{%0,%1,%2,%3};" \
        : "+f"(C0), "+f"(C1), "+f"(C2), "+f"(C3) \
        : "r"(A0), "r"(A1), "r"(A2), "r"(A3), "r"(B0), "r"(B1))

#define LDSM_X4(R0,R1,R2,R3,ADDR) \
    asm volatile("ldmatrix.sync.aligned.m8n8.x4.shared.b16 {%0,%1,%2,%3}, [%4];" \
        : "=r"(R0), "=r"(R1), "=r"(R2), "=r"(R3) : "r"(ADDR))

// ---------------- preprocessing: transpose f32 -> half [N][K] -------------
__global__ void __launch_bounds__(256) transpose_half_kernel(const float* __restrict__ in,
                                                             __half* __restrict__ out,
                                                             int K, int N, int ostride,
                                                             float scale) {
    __shared__ float t[32][33];
    const int tx = threadIdx.x, ty = threadIdx.y;   // 32 x 8
    const int n0 = blockIdx.x * 32, k0 = blockIdx.y * 32;
#pragma unroll
    for (int i = 0; i < 32; i += 8)
        t[ty + i][tx] = in[(size_t)(k0 + ty + i) * N + n0 + tx];
    __syncthreads();
#pragma unroll
    for (int i = 0; i < 32; i += 8)
        out[(size_t)(n0 + ty + i) * ostride + k0 + tx] = __float2half(scale * t[tx][ty + i]);
}

// Wff1: transpose + interleave into rows 2j / 2j+1 (a / gate), K=1024
__global__ void __launch_bounds__(256) transpose_swiglu_kernel(const float* __restrict__ in,
                                                               __half* __restrict__ out) {
    __shared__ float ta[32][33], tg[32][33];
    const int tx = threadIdx.x, ty = threadIdx.y;
    const int j0 = blockIdx.x * 32, k0 = blockIdx.y * 32;
#pragma unroll
    for (int i = 0; i < 32; i += 8) {
        ta[ty + i][tx] = in[(size_t)(k0 + ty + i) * 8192 + j0 + tx];
        tg[ty + i][tx] = in[(size_t)(k0 + ty + i) * 8192 + 4096 + j0 + tx];
    }
    __syncthreads();
#pragma unroll
    for (int i = 0; i < 32; i += 8) {
        const int jj = j0 + ty + i;
        out[(size_t)(2 * jj)     * 1024 + k0 + tx] = __float2half(ta[tx][ty + i]);
        out[(size_t)(2 * jj + 1) * 1024 + k0 + tx] = __float2half(tg[tx][ty + i]);
    }
}

// ---------------- LayerNorm (f32 in -> half out) ----------------
__global__ void __launch_bounds__(256) ln_kernel(const float* __restrict__ in,
                                                 const float* __restrict__ g,
                                                 __half* __restrict__ out) {
    const int row = blockIdx.x;
    const int t = threadIdx.x;
    const float* p = in + (size_t)row * DIM;
    float4 v = *(const float4*)&p[t * 4];
    float s  = v.x + v.y + v.z + v.w;
    float sq = v.x*v.x + v.y*v.y + v.z*v.z + v.w*v.w;
#pragma unroll
    for (int off = 16; off; off >>= 1) {
        s  += __shfl_xor_sync(0xffffffffu, s,  off);
        sq += __shfl_xor_sync(0xffffffffu, sq, off);
    }
    __shared__ float rs[8], rq[8];
    if ((t & 31) == 0) { rs[t >> 5] = s; rq[t >> 5] = sq; }
    __syncthreads();
    float ts = 0.f, tq = 0.f;
#pragma unroll
    for (int i = 0; i < 8; i++) { ts += rs[i]; tq += rq[i]; }
    const float mu  = ts * (1.f / DIM);
    const float var = tq * (1.f / DIM) - mu * mu;
    const float rstd = rsqrtf(var + 1e-5f);
    float4 gv = *(const float4*)&g[t * 4];
    __half2* op = (__half2*)&out[(size_t)row * DIM + t * 4];
    op[0] = __floats2half2_rn((v.x - mu) * rstd * gv.x, (v.y - mu) * rstd * gv.y);
    op[1] = __floats2half2_rn((v.z - mu) * rstd * gv.z, (v.w - mu) * rstd * gv.w);
}

// ============ fp16 GEMM, 256x128 tiles, 512 threads (16 warps 4m x 4n) ====
// EPI 0: store f32; EPI 5: QFF combined (q half store / SwiGLU pairs)
#define H2S 72
#define H2_STG (256*H2S + 128*H2S)
#define HG2_SMEM_BYTES (2*H2_STG*2)

template<int EPI>
__global__ void __launch_bounds__(512) hgemm2_kernel(
        int M, int N, int K, int lda,
        const __half* __restrict__ A, const __half* __restrict__ Bt,
        void* __restrict__ Cv, __half* __restrict__ Cv2) {
    extern __shared__ __half smh[];
    const int tid = threadIdx.x, lane = tid & 31, wid = tid >> 5;
    const int wm = (wid >> 2) * 64, wn = (wid & 3) * 32;
    const int bm = blockIdx.y * 256, bn = blockIdx.x * 128;
    const int gr = lane >> 2, gq = lane & 3;

    float acc[4][4][4] = {};
    const int T = K / 64;

    auto issue = [&](int t) {
        const int s = t & 1;
        const int k0 = t * 64;
        __half* As = smh + s * H2_STG;
        __half* Bs = As + 256 * H2S;
#pragma unroll
        for (int p = 0; p < 4; p++) {
            const int lin = p * 512 + tid;
            const int row = lin >> 3, q8 = (lin & 7) * 8;
            cp16(&As[row * H2S + q8], &A[(size_t)(bm + row) * lda + k0 + q8]);
        }
#pragma unroll
        for (int p = 0; p < 2; p++) {
            const int lin = p * 512 + tid;
            const int row = lin >> 3, q8 = (lin & 7) * 8;
            cp16(&Bs[row * H2S + q8], &Bt[(size_t)(bn + row) * K + k0 + q8]);
        }
        asm volatile("cp.async.commit_group;");
    };

    issue(0);
    if (T > 1) issue(1);

    const int a_r = lane & 15, a_c = (lane >> 4) << 3;
    const int b_r = (lane & 7) + ((lane >> 4) & 1) * 8;
    const int b_c = ((lane >> 3) & 1) << 3;

    for (int t = 0; t < T; t++) {
        if (t + 1 < T) asm volatile("cp.async.wait_group 1;");
        else           asm volatile("cp.async.wait_group 0;");
        __syncthreads();

        const int s = t & 1;
        const __half* As = smh + s * H2_STG;
        const __half* Bs = As + 256 * H2S;
#pragma unroll
        for (int ks = 0; ks < 4; ks++) {
            const int k = ks * 16;
            unsigned a[4][4], b[4][2];
#pragma unroll
            for (int mi = 0; mi < 4; mi++) {
                const unsigned ad = smem_u32(&As[(wm + mi * 16 + a_r) * H2S + k + a_c]);
                LDSM_X4(a[mi][0], a[mi][1], a[mi][2], a[mi][3], ad);
            }
#pragma unroll
            for (int np = 0; np < 2; np++) {
                const unsigned ad = smem_u32(&Bs[(wn + np * 16 + b_r) * H2S + k + b_c]);
                LDSM_X4(b[2*np][0], b[2*np][1], b[2*np+1][0], b[2*np+1][1], ad);
            }
#pragma unroll
            for (int mi = 0; mi < 4; mi++)
#pragma unroll
                for (int ni = 0; ni < 4; ni++)
                    MMA_F16(acc[mi][ni][0], acc[mi][ni][1], acc[mi][ni][2], acc[mi][ni][3],
                            a[mi][0], a[mi][1], a[mi][2], a[mi][3], b[ni][0], b[ni][1]);
        }
        __syncthreads();
        if (t + 2 < T) issue(t + 2);
    }

#pragma unroll
    for (int mi = 0; mi < 4; mi++) {
#pragma unroll
        for (int ni = 0; ni < 4; ni++) {
            const int row0 = bm + wm + mi * 16 + gr;
            const int col  = bn + wn + ni * 8 + 2 * gq;
            if (EPI == 0) {
                float* C = (float*)Cv;
                *(float2*)&C[(size_t)row0 * N + col] =
                    make_float2(acc[mi][ni][0], acc[mi][ni][1]);
                *(float2*)&C[(size_t)(row0 + 8) * N + col] =
                    make_float2(acc[mi][ni][2], acc[mi][ni][3]);
            } else {  // EPI == 5 : QFF
                if (bn < 1024) {
                    __half* C = (__half*)Cv;
                    *(__half2*)&C[(size_t)row0 * 1024 + col] =
                        __floats2half2_rn(acc[mi][ni][0], acc[mi][ni][1]);
                    *(__half2*)&C[(size_t)(row0 + 8) * 1024 + col] =
                        __floats2half2_rn(acc[mi][ni][2], acc[mi][ni][3]);
                } else {
                    const int colh = (col - 1024) >> 1;
                    const float g0 = acc[mi][ni][1], g1 = acc[mi][ni][3];
                    Cv2[(size_t)row0 * CATW + colh] =
                        __float2half(acc[mi][ni][0] * (g0 / (1.f + __expf(-g0))));
                    Cv2[(size_t)(row0 + 8) * CATW + colh] =
                        __float2half(acc[mi][ni][2] * (g1 / (1.f + __expf(-g1))));
                }
            }
        }
    }
}

// ---------------- kv GEMM: 128x128 tiles (N=128 only) ----------------
#define HS 40
#define HSTAGE (128*HS*2)
#define HGEMM_SMEM_BYTES (3*HSTAGE*2)

__global__ void __launch_bounds__(256) kv_gemm_kernel(
        int M, int N, int K,
        const __half* __restrict__ A, const __half* __restrict__ Bt,
        __half* __restrict__ C) {
    extern __shared__ __half smh[];
    const int tid = threadIdx.x, lane = tid & 31, wid = tid >> 5;
    const int wm = (wid & 1) * 64, wn = (wid >> 1) * 32;
    const int bm = blockIdx.y * 128, bn = blockIdx.x * 128;
    const int gr = lane >> 2, gq = lane & 3;

    float acc[4][4][4] = {};
    const int T = K / 32;

    auto issue = [&](int t) {
        const int s = t % 3;
        const int k0 = t * 32;
        __half* As = smh + s * HSTAGE;
        __half* Bs = As + 128 * HS;
#pragma unroll
        for (int p = 0; p < 2; p++) {
            const int lin = p * 256 + tid;
            const int row = lin >> 2, q8 = (lin & 3) * 8;
            cp16(&As[row * HS + q8], &A [(size_t)(bm + row) * K + k0 + q8]);
            cp16(&Bs[row * HS + q8], &Bt[(size_t)(bn + row) * K + k0 + q8]);
        }
        asm volatile("cp.async.commit_group;");
    };

    issue(0);
    if (T > 1) issue(1);

    const int a_r = lane & 15, a_c = (lane >> 4) << 3;
    const int b_r = (lane & 7) + ((lane >> 4) & 1) * 8;
    const int b_c = ((lane >> 3) & 1) << 3;

    for (int t = 0; t < T; t++) {
        if (t + 1 < T) asm volatile("cp.async.wait_group 1;");
        else           asm volatile("cp.async.wait_group 0;");
        __syncthreads();
        if (t + 2 < T) issue(t + 2);

        const int s = t % 3;
        const __half* As = smh + s * HSTAGE;
        const __half* Bs = As + 128 * HS;
#pragma unroll
        for (int ks = 0; ks < 2; ks++) {
            const int k = ks * 16;
            unsigned a[4][4], b[4][2];
#pragma unroll
            for (int mi = 0; mi < 4; mi++) {
                const unsigned ad = smem_u32(&As[(wm + mi * 16 + a_r) * HS + k + a_c]);
                LDSM_X4(a[mi][0], a[mi][1], a[mi][2], a[mi][3], ad);
            }
#pragma unroll
            for (int np = 0; np < 2; np++) {
                const unsigned ad = smem_u32(&Bs[(wn + np * 16 + b_r) * HS + k + b_c]);
                LDSM_X4(b[2*np][0], b[2*np][1], b[2*np+1][0], b[2*np+1][1], ad);
            }
#pragma unroll
            for (int mi = 0; mi < 4; mi++)
#pragma unroll
                for (int ni = 0; ni < 4; ni++)
                    MMA_F16(acc[mi][ni][0], acc[mi][ni][1], acc[mi][ni][2], acc[mi][ni][3],
                            a[mi][0], a[mi][1], a[mi][2], a[mi][3], b[ni][0], b[ni][1]);
        }
        __syncthreads();
    }

#pragma unroll
    for (int mi = 0; mi < 4; mi++) {
#pragma unroll
        for (int ni = 0; ni < 4; ni++) {
            const int row0 = bm + wm + mi * 16 + gr;
            const int col  = bn + wn + ni * 8 + 2 * gq;
            *(__half2*)&C[(size_t)row0 * N + col] =
                __floats2half2_rn(acc[mi][ni][0], acc[mi][ni][1]);
            *(__half2*)&C[(size_t)(row0 + 8) * N + col] =
                __floats2half2_rn(acc[mi][ni][2], acc[mi][ni][3]);
        }
    }
}

// ---------------- flash attention, fp16 mma + ldmatrix --------------------
#define AQS 72
#define AOFF_P  4608
#define AOFF_ST 9216
#define ASTAGE  9216
#define AOFF_MK 27648
#define ATT_SMEM_BYTES (AOFF_MK*2 + 2*64*4)

__global__ void __launch_bounds__(128) attn_kernel(const __half* __restrict__ q,
                                                   const __half* __restrict__ kv,
                                                   const int* __restrict__ mask,
                                                   __half* __restrict__ out) {
    extern __shared__ __half smh[];
    __half* sQ = smh;
    __half* sP = smh + AOFF_P;

    const int tid = threadIdx.x, lane = tid & 31, wid = tid >> 5;
    const int gr = lane >> 2, gq = lane & 3;
    const int wm = wid * 16;
    const int qt = blockIdx.x, h = blockIdx.y, b = blockIdx.z;
    const size_t qbase = ((size_t)(b * SEQ + qt * 64)) * DIM + h * DHEAD;
    const size_t obase = ((size_t)(b * SEQ + qt * 64)) * CATW + h * DHEAD;

    const int a_r = lane & 15, a_c = (lane >> 4) << 3;
    const int b_r = (lane & 7) + ((lane >> 4) & 1) * 8;
    const int b_c = ((lane >> 3) & 1) << 3;

#pragma unroll
    for (int p = 0; p < 4; p++) {
        const int lin = p * 128 + tid;
        const int r = lin >> 3, c8 = (lin & 7) * 8;
        *(uint4*)&sQ[r * AQS + c8] = *(const uint4*)&q[qbase + (size_t)r * DIM + c8];
    }

    auto issue = [&](int jt, int s) {
        __half* sK = smh + AOFF_ST + s * ASTAGE;
        __half* sV = sK + 64 * AQS;
        int*   sMk = (int*)(smh + AOFF_MK) + s * 64;
        const size_t kbase = (size_t)(b * SEQ + jt * 64) * 128;
#pragma unroll
        for (int p = 0; p < 8; p++) {
            const int lin = p * 128 + tid;
            const int j = lin >> 4, c8 = (lin & 15) * 8;
            const __half* src = &kv[kbase + (size_t)j * 128 + c8];
            if (c8 < 64) cp16(&sK[j * AQS + c8], src);
            else         cp16(&sV[j * AQS + c8 - 64], src);
        }
        if (tid < 16) cp16(&sMk[tid * 4], &mask[b * SEQ + jt * 64 + tid * 4]);
        asm volatile("cp.async.commit_group;");
    };

    issue(0, 0);

    float m0 = -1e30f, m1 = -1e30f, l0 = 0.f, l1 = 0.f;
    float o[8][4];
#pragma unroll
    for (int d = 0; d < 8; d++)
#pragma unroll
        for (int j = 0; j < 4; j++) o[d][j] = 0.f;

    for (int jt = 0; jt < SEQ / 64; jt++) {
        if (jt + 1 < SEQ / 64) {
            issue(jt + 1, (jt + 1) & 1);
            asm volatile("cp.async.wait_group 1;");
        } else {
            asm volatile("cp.async.wait_group 0;");
        }
        __syncthreads();

        const int s = jt & 1;
        const __half* sK = smh + AOFF_ST + s * ASTAGE;
        const __half* sV = sK + 64 * AQS;
        const int*   sMk = (const int*)(smh + AOFF_MK) + s * 64;

        float sc[8][4];
#pragma unroll
        for (int n = 0; n < 8; n++)
#pragma unroll
            for (int j = 0; j < 4; j++) sc[n][j] = 0.f;

#pragma unroll
        for (int ks = 0; ks < 4; ks++) {
            const int k = ks * 16;
            unsigned a0, a1, a2, a3;
            LDSM_X4(a0, a1, a2, a3, smem_u32(&sQ[(wm + a_r) * AQS + k + a_c]));
#pragma unroll
            for (int np = 0; np < 4; np++) {
                unsigned b0, b1, b2, b3;
                LDSM_X4(b0, b1, b2, b3, smem_u32(&sK[(np * 16 + b_r) * AQS + k + b_c]));
                MMA_F16(sc[2*np][0], sc[2*np][1], sc[2*np][2], sc[2*np][3],
                        a0, a1, a2, a3, b0, b1);
                MMA_F16(sc[2*np+1][0], sc[2*np+1][1], sc[2*np+1][2], sc[2*np+1][3],
                        a0, a1, a2, a3, b2, b3);
            }
        }

#pragma unroll
        for (int n = 0; n < 8; n++) {
            const int c0 = n * 8 + 2 * gq;
            if (sMk[c0] == 0)     { sc[n][0] = -1e30f; sc[n][2] = -1e30f; }
            if (sMk[c0 + 1] == 0) { sc[n][1] = -1e30f; sc[n][3] = -1e30f; }
        }
        float mx0 = -1e30f, mx1 = -1e30f;
#pragma unroll
        for (int n = 0; n < 8; n++) {
            mx0 = fmaxf(mx0, fmaxf(sc[n][0], sc[n][1]));
            mx1 = fmaxf(mx1, fmaxf(sc[n][2], sc[n][3]));
        }
        mx0 = fmaxf(mx0, __shfl_xor_sync(0xffffffffu, mx0, 1));
        mx0 = fmaxf(mx0, __shfl_xor_sync(0xffffffffu, mx0, 2));
        mx1 = fmaxf(mx1, __shfl_xor_sync(0xffffffffu, mx1, 1));
        mx1 = fmaxf(mx1, __shfl_xor_sync(0xffffffffu, mx1, 2));
        const float mn0 = fmaxf(m0, mx0), mn1 = fmaxf(m1, mx1);
        const float corr0 = __expf(m0 - mn0), corr1 = __expf(m1 - mn1);
        float rs0 = 0.f, rs1 = 0.f;
#pragma unroll
        for (int n = 0; n < 8; n++) {
            float p0 = __expf(sc[n][0] - mn0);
            float p1 = __expf(sc[n][1] - mn0);
            float p2 = __expf(sc[n][2] - mn1);
            float p3 = __expf(sc[n][3] - mn1);
            rs0 += p0 + p1; rs1 += p2 + p3;
            *(__half2*)&sP[(wm + gr) * AQS + n * 8 + 2 * gq] = __floats2half2_rn(p0, p1);
            *(__half2*)&sP[(wm + gr + 8) * AQS + n * 8 + 2 * gq] = __floats2half2_rn(p2, p3);
        }
        rs0 += __shfl_xor_sync(0xffffffffu, rs0, 1);
        rs0 += __shfl_xor_sync(0xffffffffu, rs0, 2);
        rs1 += __shfl_xor_sync(0xffffffffu, rs1, 1);
        rs1 += __shfl_xor_sync(0xffffffffu, rs1, 2);
        l0 = l0 * corr0 + rs0; m0 = mn0;
        l1 = l1 * corr1 + rs1; m1 = mn1;
#pragma unroll
        for (int d = 0; d < 8; d++) {
            o[d][0] *= corr0; o[d][1] *= corr0;
            o[d][2] *= corr1; o[d][3] *= corr1;
        }
        __syncwarp();

#pragma unroll
        for (int ks = 0; ks < 4; ks++) {
            const int kc = ks * 16;
            unsigned a0, a1, a2, a3;
            LDSM_X4(a0, a1, a2, a3, smem_u32(&sP[(wm + a_r) * AQS + kc + a_c]));
            const int vrow = kc + (lane & 7) + ((lane >> 3) & 1) * 8;
            const int vcb  = ((lane >> 4) & 1) * 8;
#pragma unroll
            for (int dp = 0; dp < 4; dp++) {
                unsigned b0, b1, b2, b3;
                const unsigned addr = smem_u32(&sV[vrow * AQS + dp * 16 + vcb]);
                asm volatile(
                    "ldmatrix.sync.aligned.m8n8.x4.trans.shared.b16 {%0,%1,%2,%3}, [%4];"
                    : "=r"(b0), "=r"(b1), "=r"(b2), "=r"(b3) : "r"(addr));
                MMA_F16(o[dp*2][0], o[dp*2][1], o[dp*2][2], o[dp*2][3],
                        a0, a1, a2, a3, b0, b1);
                MMA_F16(o[dp*2+1][0], o[dp*2+1][1], o[dp*2+1][2], o[dp*2+1][3],
                        a0, a1, a2, a3, b2, b3);
            }
        }
        __syncthreads();
    }

    const float inv0 = 1.f / l0, inv1 = 1.f / l1;
#pragma unroll
    for (int dt = 0; dt < 8; dt++) {
        const int col = dt * 8 + 2 * gq;
        *(__half2*)&out[obase + (size_t)(wm + gr) * CATW + col] =
            __floats2half2_rn(o[dt][0] * inv0, o[dt][1] * inv0);
        *(__half2*)&out[obase + (size_t)(wm + gr + 8) * CATW + col] =
            __floats2half2_rn(o[dt][2] * inv1, o[dt][3] * inv1);
    }
}

// ---------------- launch --------------------------------------------------
extern "C" void kernel_launch(void* const* d_in, const int* in_sizes, int n_in,
                              void* d_out, int out_size) {
    (void)in_sizes; (void)n_in; (void)out_size;
    const float* x        = (const float*)d_in[0];
    const float* context  = (const float*)d_in[1];
    const int*   mask     = (const int*)  d_in[2];
    const float* gamma    = (const float*)d_in[3];
    const float* ctxgamma = (const float*)d_in[4];
    const float* Wq       = (const float*)d_in[5];
    const float* Wkv      = (const float*)d_in[6];
    const float* Wout     = (const float*)d_in[7];
    const float* Wff1     = (const float*)d_in[8];
    const float* Wff2     = (const float*)d_in[9];
    float* out = (float*)d_out;

    __half *xn, *cn, *qb, *kvb, *cat, *w;
    cudaGetSymbolAddress((void**)&xn,  g_xn);
    cudaGetSymbolAddress((void**)&cn,  g_cn);
    cudaGetSymbolAddress((void**)&qb,  g_q);
    cudaGetSymbolAddress((void**)&kvb, g_kv);
    cudaGetSymbolAddress((void**)&cat, g_cat);
    cudaGetSymbolAddress((void**)&w,   g_w);

    cudaFuncSetAttribute(attn_kernel, cudaFuncAttributeMaxDynamicSharedMemorySize, ATT_SMEM_BYTES);
    cudaFuncSetAttribute(kv_gemm_kernel, cudaFuncAttributeMaxDynamicSharedMemorySize, HGEMM_SMEM_BYTES);
    cudaFuncSetAttribute(hgemm2_kernel<0>, cudaFuncAttributeMaxDynamicSharedMemorySize, HG2_SMEM_BYTES);
    cudaFuncSetAttribute(hgemm2_kernel<5>, cudaFuncAttributeMaxDynamicSharedMemorySize, HG2_SMEM_BYTES);

    cudaStream_t s1;
    cudaStreamCreateWithFlags(&s1, cudaStreamNonBlocking);
    cudaEvent_t eFork, eWT, eJoin;
    cudaEventCreateWithFlags(&eFork, cudaEventDisableTiming);
    cudaEventCreateWithFlags(&eWT,   cudaEventDisableTiming);
    cudaEventCreateWithFlags(&eJoin, cudaEventDisableTiming);

    dim3 tb(32, 8);

    cudaEventRecord(eFork, 0);
    cudaStreamWaitEvent(s1, eFork, 0);

    // ---- side stream starts immediately: QFF weight prep (no data deps) ----
    transpose_half_kernel<<<dim3(1024/32, 1024/32), tb, 0, s1>>>(Wq, w + WQFF_OFF, 1024, 1024, 1024, 0.125f);
    transpose_swiglu_kernel<<<dim3(4096/32, 1024/32), tb, 0, s1>>>(Wff1, w + WQFF_OFF + 1024*1024);
    cudaEventRecord(eWT, s1);

    // ---- main stream: ln_x (concurrent with weight transposes) -> QFF ----
    ln_kernel<<<ROWS, 256>>>(x, gamma, xn);
    cudaStreamWaitEvent(0, eWT, 0);
    hgemm2_kernel<5><<<dim3(9216/128, ROWS/256), 512, HG2_SMEM_BYTES>>>(
        ROWS, 9216, DIM, DIM, xn, w + WQFF_OFF, qb, cat + 1024);

    // ---- side stream (overlaps QFF): ctx chain + OUT weight prep ----
    ln_kernel<<<ROWS, 256, 0, s1>>>(context, ctxgamma, cn);
    transpose_half_kernel<<<dim3(128/32, 1024/32), tb, 0, s1>>>(Wkv, w + WKV_OFF, 1024, 128, 1024, 1.f);
    kv_gemm_kernel<<<dim3(1, ROWS/128), 256, HGEMM_SMEM_BYTES, s1>>>(
        ROWS, 2*DHEAD, DIM, cn, w + WKV_OFF, kvb);
    transpose_half_kernel<<<dim3(1024/32, 1024/32), tb, 0, s1>>>(Wout, w + WOUT2_OFF, 1024, 1024, CATW, 1.f);
    transpose_half_kernel<<<dim3(1024/32, 4096/32), tb, 0, s1>>>(Wff2, w + WOUT2_OFF + 1024, 4096, 1024, CATW, 1.f);
    cudaEventRecord(eJoin, s1);

    // ---- join, then attention + combined OUT GEMM on main stream ----
    cudaStreamWaitEvent(0, eJoin, 0);
    attn_kernel<<<dim3(SEQ/64, HEADS, BATCH), 128, ATT_SMEM_BYTES>>>(qb, kvb, mask, cat);
    hgemm2_kernel<0><<<dim3(DIM/128, ROWS/256), 512, HG2_SMEM_BYTES>>>(
        ROWS, DIM, CATW, CATW, cat, w + WOUT2_OFF, out, nullptr);

    cudaEventDestroy(eFork);
    cudaEventDestroy(eWT);
    cudaEventDestroy(eJoin);
    cudaStreamDestroy(s1);
}